// round 3
// baseline (speedup 1.0000x reference)
#include <cuda_runtime.h>
#include <math_constants.h>

// Shapes fixed by the problem
#define B_  32
#define T_  12
#define N_  512
#define F_  64
#define H_  64

#define BLOCKS 512
#define THREADS 256
#define WARPS   8
#define PAIRS_PER_WARP  4      // 512 blocks * 8 warps * 4 pairs = 16384 = B*N
#define PAIRS_PER_BLOCK 32

// Per-block partial 12x12 gram matrices (overwritten every launch; no zeroing needed)
__device__ float g_partial[BLOCKS * 144];
// Ticket counter: zero at module load; last block resets it to 0 each launch,
// so every graph replay starts from a clean state (deterministic).
__device__ unsigned int g_ticket;

__global__ __launch_bounds__(THREADS) void fft_sel_fused(
    const float* __restrict__ x,   // [B,T,N,F]
    const float* __restrict__ Wq,  // [F,H]
    const float* __restrict__ bq,  // [H]
    const float* __restrict__ Wk,  // [F,H]
    const float* __restrict__ bk,  // [H]
    float* __restrict__ out, int out_n)
{
    __shared__ float s_wq[F_], s_wk[F_];
    __shared__ float s_bsum[2];
    __shared__ float s_q[PAIRS_PER_BLOCK * T_];
    __shared__ float s_k[PAIRS_PER_BLOCK * T_];
    __shared__ float s_score[144];
    __shared__ bool  s_last;

    const int tid = threadIdx.x;

    // ---- Pre-sum weights over H (exact collapse of FFT/irfft/mean-H) ----
    if (tid < F_) {
        float aq = 0.f, ak = 0.f;
#pragma unroll
        for (int h = 0; h < H_; h++) {
            aq += Wq[tid * H_ + h];
            ak += Wk[tid * H_ + h];
        }
        s_wq[tid] = aq;
        s_wk[tid] = ak;
    } else if (tid == 64) {
        float a = 0.f;
#pragma unroll
        for (int h = 0; h < H_; h++) a += bq[h];
        s_bsum[0] = a;
    } else if (tid == 65) {
        float a = 0.f;
#pragma unroll
        for (int h = 0; h < H_; h++) a += bk[h];
        s_bsum[1] = a;
    }
    __syncthreads();

    const int wid  = tid >> 5;
    const int lane = tid & 31;
    const int half = lane >> 4;   // which of 2 rows this half-warp handles
    const int fl   = lane & 15;   // float4 index within a 64-float row

    const float4 wq4 = ((const float4*)s_wq)[fl];
    const float4 wk4 = ((const float4*)s_wk)[fl];
    const float bqs = s_bsum[0];
    const float bks = s_bsum[1];

    const int warpPairBase = (blockIdx.x * WARPS + wid) * PAIRS_PER_WARP;

    // ---- Main streaming phase: sq/sk row sums for 32 (b,n) pairs ----
#pragma unroll
    for (int pl = 0; pl < PAIRS_PER_WARP; pl++) {
        const int gp = warpPairBase + pl;     // global (b,n) pair
        const int b  = gp >> 9;               // /512
        const int n  = gp & 511;
        const float4* rowp =
            (const float4*)(x + ((size_t)(b * T_ + half) * N_ + n) * F_) + fl;

#pragma unroll
        for (int tt = 0; tt < T_ / 2; tt++) {
            const float4 v = rowp[(size_t)tt * (2 * N_ * F_ / 4)];
            float aq = v.x * wq4.x + v.y * wq4.y + v.z * wq4.z + v.w * wq4.w;
            float ak = v.x * wk4.x + v.y * wk4.y + v.z * wk4.z + v.w * wk4.w;
#pragma unroll
            for (int s = 8; s >= 1; s >>= 1) {
                aq += __shfl_xor_sync(0xffffffffu, aq, s);
                ak += __shfl_xor_sync(0xffffffffu, ak, s);
            }
            if (fl == 0) {
                const int t = tt * 2 + half;
                const int e = wid * PAIRS_PER_WARP + pl;   // 0..31
                s_q[e * T_ + t] = aq + bqs;
                s_k[e * T_ + t] = ak + bks;
            }
        }
    }
    __syncthreads();

    // ---- Block-local 12x12 gram over the 32 staged (b,n) pairs ----
    if (tid < 144) {
        const int i = tid / 12;
        const int j = tid - i * 12;
        float acc = 0.f;
#pragma unroll 8
        for (int e = 0; e < PAIRS_PER_BLOCK; e++)
            acc += s_q[e * T_ + i] * s_k[e * T_ + j];
        g_partial[blockIdx.x * 144 + tid] = acc;
    }

    // ---- Last-block reduction ticket ----
    __threadfence();          // publish g_partial writes
    __syncthreads();
    if (tid == 0) {
        unsigned int old = atomicAdd(&g_ticket, 1u);
        s_last = (old == BLOCKS - 1u);
    }
    __syncthreads();
    if (!s_last) return;

    __threadfence();          // acquire all blocks' g_partial

    // ---- Final reduction: 512 partials -> 12x12 scores ----
    if (tid < 144) {
        float a = 0.f;
#pragma unroll 16
        for (int e = 0; e < BLOCKS; e++)
            a += g_partial[e * 144 + tid];
        // mean over (B, N, H) = / (32*512*64)
        s_score[tid] = a * (1.0f / 1048576.0f);
    }
    __syncthreads();

    if (tid == 0) g_ticket = 0u;   // reset for next graph replay

    // ---- Row-wise top-k (tau from out_size), jax tie-break = lowest index ----
    int tau;
    bool write_idx;
    if (out_n >= 2 * T_ && (out_n % (2 * T_)) == 0) {
        tau = out_n / (2 * T_);
        write_idx = true;
    } else {
        tau = out_n / T_;
        write_idx = false;
    }
    if (tau > T_) tau = T_;

    if (tid < T_) {
        const int i = tid;
        float v[T_];
#pragma unroll
        for (int j = 0; j < T_; j++) v[j] = s_score[i * 12 + j];
        unsigned usedmask = 0u;
        for (int r = 0; r < tau; r++) {
            float best = -CUDART_INF_F;
            int bj = 0;
#pragma unroll
            for (int j = 0; j < T_; j++) {
                bool ok = ((usedmask >> j) & 1u) == 0u && v[j] > best;
                if (ok) { best = v[j]; bj = j; }
            }
            usedmask |= (1u << bj);
            out[i * tau + r] = best;
            if (write_idx) out[T_ * tau + i * tau + r] = (float)bj;
        }
    }
}

extern "C" void kernel_launch(void* const* d_in, const int* in_sizes, int n_in,
                              void* d_out, int out_size)
{
    const float* x  = (const float*)d_in[0];
    const float* Wq = (const float*)d_in[1];
    const float* bq = (const float*)d_in[2];
    const float* Wk = (const float*)d_in[3];
    const float* bk = (const float*)d_in[4];
    (void)in_sizes; (void)n_in;

    fft_sel_fused<<<BLOCKS, THREADS>>>(x, Wq, bq, Wk, bk, (float*)d_out, out_size);
}

// round 4
// speedup vs baseline: 2.9512x; 2.9512x over previous
#include <cuda_runtime.h>
#include <math_constants.h>

// Shapes fixed by the problem
#define B_  32
#define T_  12
#define N_  512
#define F_  64
#define H_  64

#define BLOCKS 256
#define THREADS 256
#define WARPS   8
#define PAIRS_PER_WARP  8      // 256 blocks * 8 warps * 8 pairs = 16384 = B*N
#define PAIRS_PER_BLOCK 64

// Per-block partial 12x12 gram matrices (overwritten every launch; no zeroing needed)
__device__ float g_partial[BLOCKS * 144];
// Ticket: zero at module load; last block resets to 0 each launch -> every
// graph replay starts clean (deterministic).
__device__ unsigned int g_ticket;

__global__ __launch_bounds__(THREADS) void fft_sel_fused(
    const float* __restrict__ x,   // [B,T,N,F]
    const float* __restrict__ Wq,  // [F,H]
    const float* __restrict__ bq,  // [H]
    const float* __restrict__ Wk,  // [F,H]
    const float* __restrict__ bk,  // [H]
    float* __restrict__ out, int out_n)
{
    __shared__ float s_wq[F_], s_wk[F_];
    __shared__ float s_bsum[2];
    __shared__ float s_q[PAIRS_PER_BLOCK * T_];
    __shared__ float s_k[PAIRS_PER_BLOCK * T_];
    __shared__ float s_score[144];
    __shared__ bool  s_last;

    const int tid  = threadIdx.x;
    const int wid  = tid >> 5;
    const int lane = tid & 31;

    // ---- Coalesced pre-sum of weights over H ----
    // warp w handles rows f = 8w .. 8w+7 of both Wq and Wk.
    {
#pragma unroll
        for (int r = 0; r < 8; r++) {
            const int f = wid * 8 + r;
            float aq = Wq[f * H_ + lane] + Wq[f * H_ + 32 + lane];
            float ak = Wk[f * H_ + lane] + Wk[f * H_ + 32 + lane];
#pragma unroll
            for (int s = 16; s >= 1; s >>= 1) {
                aq += __shfl_xor_sync(0xffffffffu, aq, s);
                ak += __shfl_xor_sync(0xffffffffu, ak, s);
            }
            if (lane == 0) { s_wq[f] = aq; s_wk[f] = ak; }
        }
        if (wid == 0) {
            float a = bq[lane] + bq[32 + lane];
#pragma unroll
            for (int s = 16; s >= 1; s >>= 1) a += __shfl_xor_sync(0xffffffffu, a, s);
            if (lane == 0) s_bsum[0] = a;
        } else if (wid == 1) {
            float a = bk[lane] + bk[32 + lane];
#pragma unroll
            for (int s = 16; s >= 1; s >>= 1) a += __shfl_xor_sync(0xffffffffu, a, s);
            if (lane == 0) s_bsum[1] = a;
        }
    }
    __syncthreads();

    const int half = lane >> 4;   // which of 2 rows this half-warp handles
    const int fl   = lane & 15;   // float4 index within a 64-float row

    const float4 wq4 = ((const float4*)s_wq)[fl];
    const float4 wk4 = ((const float4*)s_wk)[fl];
    const float bqs = s_bsum[0];
    const float bks = s_bsum[1];

    const int warpPairBase = (blockIdx.x * WARPS + wid) * PAIRS_PER_WARP;

    // ---- Main streaming phase: sq/sk row sums for 64 (b,n) pairs ----
#pragma unroll
    for (int pl = 0; pl < PAIRS_PER_WARP; pl++) {
        const int gp = warpPairBase + pl;     // global (b,n) pair
        const int b  = gp >> 9;               // /512
        const int n  = gp & 511;
        const float4* rowp =
            (const float4*)(x + ((size_t)(b * T_ + half) * N_ + n) * F_) + fl;

#pragma unroll
        for (int tt = 0; tt < T_ / 2; tt++) {
            const float4 v = rowp[(size_t)tt * (2 * N_ * F_ / 4)];
            float aq = v.x * wq4.x + v.y * wq4.y + v.z * wq4.z + v.w * wq4.w;
            float ak = v.x * wk4.x + v.y * wk4.y + v.z * wk4.z + v.w * wk4.w;
#pragma unroll
            for (int s = 8; s >= 1; s >>= 1) {
                aq += __shfl_xor_sync(0xffffffffu, aq, s);
                ak += __shfl_xor_sync(0xffffffffu, ak, s);
            }
            if (fl == 0) {
                const int t = tt * 2 + half;
                const int e = wid * PAIRS_PER_WARP + pl;   // 0..63
                s_q[e * T_ + t] = aq + bqs;
                s_k[e * T_ + t] = ak + bks;
            }
        }
    }
    __syncthreads();

    // ---- Block-local 12x12 gram over the 64 staged (b,n) pairs ----
    if (tid < 144) {
        const int i = tid / 12;
        const int j = tid - i * 12;
        float acc = 0.f;
#pragma unroll 8
        for (int e = 0; e < PAIRS_PER_BLOCK; e++)
            acc += s_q[e * T_ + i] * s_k[e * T_ + j];
        g_partial[blockIdx.x * 144 + tid] = acc;
    }

    // ---- Last-block ticket ----
    __threadfence();          // publish g_partial
    __syncthreads();
    if (tid == 0) {
        unsigned int old = atomicAdd(&g_ticket, 1u);
        s_last = (old == BLOCKS - 1u);
    }
    __syncthreads();
    if (!s_last) return;

    __threadfence();          // acquire all blocks' g_partial

    // ---- Final reduction: 256 partials -> 12x12 scores ----
    if (tid < 144) {
        float a = 0.f;
#pragma unroll 16
        for (int e = 0; e < BLOCKS; e++)
            a += g_partial[e * 144 + tid];
        // mean over (B, N, H) = / (32*512*64)
        s_score[tid] = a * (1.0f / 1048576.0f);
    }
    __syncthreads();

    if (tid == 0) g_ticket = 0u;   // reset for next graph replay

    // ---- Row-wise top-k (tau from out_size), jax tie-break = lowest index ----
    int tau;
    bool write_idx;
    if (out_n >= 2 * T_ && (out_n % (2 * T_)) == 0) {
        tau = out_n / (2 * T_);
        write_idx = true;
    } else {
        tau = out_n / T_;
        write_idx = false;
    }
    if (tau > T_) tau = T_;

    if (tid < T_) {
        const int i = tid;
        float v[T_];
#pragma unroll
        for (int j = 0; j < T_; j++) v[j] = s_score[i * 12 + j];
        unsigned usedmask = 0u;
        for (int r = 0; r < tau; r++) {
            float best = -CUDART_INF_F;
            int bj = 0;
#pragma unroll
            for (int j = 0; j < T_; j++) {
                bool ok = ((usedmask >> j) & 1u) == 0u && v[j] > best;
                if (ok) { best = v[j]; bj = j; }
            }
            usedmask |= (1u << bj);
            out[i * tau + r] = best;
            if (write_idx) out[T_ * tau + i * tau + r] = (float)bj;
        }
    }
}

extern "C" void kernel_launch(void* const* d_in, const int* in_sizes, int n_in,
                              void* d_out, int out_size)
{
    const float* x  = (const float*)d_in[0];
    const float* Wq = (const float*)d_in[1];
    const float* bq = (const float*)d_in[2];
    const float* Wk = (const float*)d_in[3];
    const float* bk = (const float*)d_in[4];
    (void)in_sizes; (void)n_in;

    fft_sel_fused<<<BLOCKS, THREADS>>>(x, Wq, bq, Wk, bk, (float*)d_out, out_size);
}